// round 3
// baseline (speedup 1.0000x reference)
#include <cuda_runtime.h>
#include <cuda_bf16.h>
#include <math.h>

#define BQ   2048
#define NST  65536
#define HD   1024
#define TOPK 8
#define NCAND 32

// ---------------- scratch (static device globals; no runtime allocation) ----------------
__device__ float          g_WkT[HD * HD];
__device__ float          g_WvT[HD * HD];
__device__ float          g_WoT[HD * HD];
__device__ float          g_keys[(size_t)NST * HD];          // 256 MB
__device__ float          g_scores[(size_t)BQ * NST];        // 512 MB
__device__ __nv_bfloat16  g_storebf[(size_t)NST * HD];       // 128 MB
__device__ __nv_bfloat16  g_qkbf[BQ * HD];
__device__ float          g_qk[BQ * HD];
__device__ float          g_qinvf[BQ];
__device__ double         g_qinvd[BQ];
__device__ double         g_wd[NST];
__device__ double         g_kinvd[NST];
__device__ float          g_cf[NST];
__device__ double         g_partiald[256];
__device__ double         g_Sd[1];
__device__ int            g_cand[BQ * NCAND];
__device__ float          g_attn[BQ * TOPK];
__device__ int            g_topi[BQ * TOPK];
__device__ float          g_u[BQ * HD];
__device__ float          g_t[BQ * HD];

// ---------------- small helpers ----------------
__device__ __forceinline__ unsigned smem_u32(const void* p) {
    return (unsigned)__cvta_generic_to_shared(p);
}

__device__ __forceinline__ void ldsm_x4(unsigned& r0, unsigned& r1, unsigned& r2, unsigned& r3,
                                        unsigned addr) {
    asm volatile("ldmatrix.sync.aligned.m8n8.x4.shared.b16 {%0,%1,%2,%3}, [%4];"
                 : "=r"(r0), "=r"(r1), "=r"(r2), "=r"(r3) : "r"(addr));
}

__device__ __forceinline__ void mma16816(float* d, const unsigned* a, const unsigned* b) {
    asm volatile(
        "mma.sync.aligned.m16n8k16.row.col.f32.bf16.bf16.f32 "
        "{%0,%1,%2,%3}, {%4,%5,%6,%7}, {%8,%9}, {%0,%1,%2,%3};"
        : "+f"(d[0]), "+f"(d[1]), "+f"(d[2]), "+f"(d[3])
        : "r"(a[0]), "r"(a[1]), "r"(a[2]), "r"(a[3]), "r"(b[0]), "r"(b[1]));
}

// ---------------- fp32 -> bf16 conversion ----------------
__global__ void tobf16_kernel(const float* __restrict__ in, __nv_bfloat16* __restrict__ out,
                              size_t n4) {
    size_t i = (size_t)blockIdx.x * blockDim.x + threadIdx.x;
    if (i >= n4) return;
    float4 v = ((const float4*)in)[i];
    __nv_bfloat162* o2 = (__nv_bfloat162*)out;
    o2[i * 2 + 0] = __floats2bfloat162_rn(v.x, v.y);
    o2[i * 2 + 1] = __floats2bfloat162_rn(v.z, v.w);
}

// ---------------- transpose (dims multiples of 32) ----------------
__global__ void transpose_kernel(const float* __restrict__ in, float* __restrict__ out,
                                 int rows, int cols) {
    __shared__ float tile[32][33];
    int x0 = blockIdx.x * 32;
    int y0 = blockIdx.y * 32;
    int tx = threadIdx.x, ty = threadIdx.y;
    #pragma unroll
    for (int r = ty; r < 32; r += 8)
        tile[r][tx] = in[(size_t)(y0 + r) * cols + (x0 + tx)];
    __syncthreads();
    #pragma unroll
    for (int r = ty; r < 32; r += 8)
        out[(size_t)(x0 + r) * rows + (y0 + tx)] = tile[tx][r];
}

// ---------------- weights in fp64 + partial sums ----------------
__global__ void weight_partial_kernel(const float* __restrict__ imp,
                                      const float* __restrict__ ts,
                                      double* __restrict__ wd,
                                      double* __restrict__ partial) {
    __shared__ double sm[256];
    int j = blockIdx.x * 256 + threadIdx.x;
    double age = 1.0 - (double)ts[j];
    double r = exp(-fabs(age) * 0.01);
    double wv = r * ((double)imp[j] + 1.0);
    wd[j] = wv;
    sm[threadIdx.x] = wv;
    __syncthreads();
    for (int s = 128; s > 0; s >>= 1) {
        if (threadIdx.x < s) sm[threadIdx.x] += sm[threadIdx.x + s];
        __syncthreads();
    }
    if (threadIdx.x == 0) partial[blockIdx.x] = sm[0];
}

__global__ void weight_sum_kernel(const double* __restrict__ partial, double* __restrict__ S) {
    __shared__ double sm[256];
    sm[threadIdx.x] = partial[threadIdx.x];
    __syncthreads();
    for (int s = 128; s > 0; s >>= 1) {
        if (threadIdx.x < s) sm[threadIdx.x] += sm[threadIdx.x + s];
        __syncthreads();
    }
    if (threadIdx.x == 0) S[0] = sm[0] + 1e-8;
}

// ---------------- per-row 1/max(||q||, eps) in fp64 ----------------
__global__ void qinv_kernel(const float* __restrict__ q,
                            float* __restrict__ qinvf, double* __restrict__ qinvd) {
    __shared__ double sm[128];
    int b = blockIdx.x;
    const float* row = q + (size_t)b * HD;
    double acc = 0.0;
    for (int h = threadIdx.x; h < HD; h += 128) { double v = row[h]; acc += v * v; }
    sm[threadIdx.x] = acc;
    __syncthreads();
    for (int s = 64; s > 0; s >>= 1) {
        if (threadIdx.x < s) sm[threadIdx.x] += sm[threadIdx.x + s];
        __syncthreads();
    }
    if (threadIdx.x == 0) {
        double n = sqrt(sm[0]);
        double inv = 1.0 / fmax(n, 1e-12);
        qinvd[b] = inv;
        qinvf[b] = (float)inv;
    }
}

// ---------------- key norms (fp64) + screening column scale ----------------
__global__ void cscale_kernel(const float* __restrict__ keys, const double* __restrict__ wd,
                              const double* __restrict__ S,
                              double* __restrict__ kinvd, float* __restrict__ cf) {
    __shared__ double sm[128];
    int j = blockIdx.x;
    const float* row = keys + (size_t)j * HD;
    double acc = 0.0;
    for (int h = threadIdx.x; h < HD; h += 128) { double v = row[h]; acc += v * v; }
    sm[threadIdx.x] = acc;
    __syncthreads();
    for (int s = 64; s > 0; s >>= 1) {
        if (threadIdx.x < s) sm[threadIdx.x] += sm[threadIdx.x + s];
        __syncthreads();
    }
    if (threadIdx.x == 0) {
        double n = sqrt(sm[0]);
        double inv = 1.0 / fmax(n, 1e-12);
        kinvd[j] = inv;
        cf[j] = (float)(wd[j] / S[0] * inv);
    }
}

// ---------------- generic fp32 SGEMM: C[M,Nn] = A[M,Kk] @ B[Kk,Nn] ----------------
__global__ __launch_bounds__(256) void sgemm_kernel(
    const float* __restrict__ A, const float* __restrict__ Bm, float* __restrict__ C,
    int M, int Nn, int Kk,
    const float* __restrict__ rowScale, const float* __restrict__ colScale) {
    __shared__ float As[8][128];
    __shared__ float Bs[8][128];
    const int tid  = threadIdx.x;
    const int crow = blockIdx.y * 128;
    const int ccol = blockIdx.x * 128;
    const int tr = (tid / 16) * 8;
    const int tc = (tid % 16) * 8;
    const int aRow = tid >> 1, aCol = (tid & 1) * 4;
    const int bRow = tid >> 5, bCol = (tid & 31) * 4;
    const float* Ag = A + (size_t)(crow + aRow) * Kk + aCol;
    const float* Bg = Bm + (size_t)bRow * Nn + ccol + bCol;

    float acc[8][8];
    #pragma unroll
    for (int i = 0; i < 8; i++)
        #pragma unroll
        for (int j = 0; j < 8; j++) acc[i][j] = 0.0f;

    for (int k0 = 0; k0 < Kk; k0 += 8) {
        float4 av = *(const float4*)(Ag + k0);
        As[aCol + 0][aRow] = av.x;
        As[aCol + 1][aRow] = av.y;
        As[aCol + 2][aRow] = av.z;
        As[aCol + 3][aRow] = av.w;
        float4 bv = *(const float4*)(Bg + (size_t)k0 * Nn);
        *(float4*)(&Bs[bRow][bCol]) = bv;
        __syncthreads();
        #pragma unroll
        for (int k = 0; k < 8; k++) {
            float ar[8], br[8];
            *(float4*)(ar)     = *(const float4*)(&As[k][tr]);
            *(float4*)(ar + 4) = *(const float4*)(&As[k][tr + 4]);
            *(float4*)(br)     = *(const float4*)(&Bs[k][tc]);
            *(float4*)(br + 4) = *(const float4*)(&Bs[k][tc + 4]);
            #pragma unroll
            for (int i = 0; i < 8; i++)
                #pragma unroll
                for (int j = 0; j < 8; j++)
                    acc[i][j] += ar[i] * br[j];
        }
        __syncthreads();
    }

    #pragma unroll
    for (int i = 0; i < 8; i++) {
        float rs = rowScale ? rowScale[crow + tr + i] : 1.0f;
        float v[8];
        #pragma unroll
        for (int j = 0; j < 8; j++) {
            v[j] = acc[i][j] * rs;
            if (colScale) v[j] *= colScale[ccol + tc + j];
        }
        float* Crow = C + (size_t)(crow + tr + i) * Nn + ccol + tc;
        *(float4*)(Crow)     = *(float4*)(v);
        *(float4*)(Crow + 4) = *(float4*)(v + 4);
    }
}

// ---------------- bf16 tensor-core screening GEMM ----------------
// C[M,N] = A[M,K] @ B[N,K]^T, col-scaled.  M=BQ, N=NST, K=HD.
// Tiles: 128x128x32, 8 warps of 64x32, m16n8k16 HMMA.
__global__ __launch_bounds__(256, 2) void scores_bf16_kernel(
    const __nv_bfloat16* __restrict__ A,   // [BQ][HD]
    const __nv_bfloat16* __restrict__ B,   // [NST][HD]
    const float* __restrict__ colScale,    // [NST]
    float* __restrict__ C)                 // [BQ][NST]
{
    __shared__ __nv_bfloat16 As[2][128][40];   // 80B row pitch: 16B-aligned + ldmatrix conflict-free
    __shared__ __nv_bfloat16 Bs[2][128][40];

    const int tid  = threadIdx.x;
    const int lane = tid & 31;
    const int wid  = tid >> 5;
    const int wm0  = (wid >> 2) * 64;
    const int wn0  = (wid & 3) * 32;
    const int bM   = blockIdx.y * 128;
    const int bN   = blockIdx.x * 128;

    const int v0 = tid, v1 = tid + 256;
    const int r0v = v0 >> 2, c0v = (v0 & 3) * 8;
    const int r1v = v1 >> 2, c1v = (v1 & 3) * 8;
    const __nv_bfloat16* Ag0 = A + (size_t)(bM + r0v) * HD + c0v;
    const __nv_bfloat16* Ag1 = A + (size_t)(bM + r1v) * HD + c1v;
    const __nv_bfloat16* Bg0 = B + (size_t)(bN + r0v) * HD + c0v;
    const __nv_bfloat16* Bg1 = B + (size_t)(bN + r1v) * HD + c1v;

    // ldmatrix source coordinates
    const int rA = (lane & 7) + ((lane >> 3) & 1) * 8;
    const int cA = (lane >> 4) * 8;
    const int rB = (lane & 7) + (lane >> 4) * 8;
    const int cB = ((lane >> 3) & 1) * 8;

    float acc[4][4][4];
    #pragma unroll
    for (int im = 0; im < 4; im++)
        #pragma unroll
        for (int in = 0; in < 4; in++)
            #pragma unroll
            for (int e = 0; e < 4; e++) acc[im][in][e] = 0.0f;

    uint4 pa0 = *(const uint4*)Ag0;
    uint4 pa1 = *(const uint4*)Ag1;
    uint4 pb0 = *(const uint4*)Bg0;
    uint4 pb1 = *(const uint4*)Bg1;
    *(uint4*)&As[0][r0v][c0v] = pa0;
    *(uint4*)&As[0][r1v][c1v] = pa1;
    *(uint4*)&Bs[0][r0v][c0v] = pb0;
    *(uint4*)&Bs[0][r1v][c1v] = pb1;
    __syncthreads();

    const int NT = HD / 32;
    for (int kt = 0; kt < NT; kt++) {
        const int buf = kt & 1;
        if (kt + 1 < NT) {
            const int ko = (kt + 1) * 32;
            pa0 = *(const uint4*)(Ag0 + ko);
            pa1 = *(const uint4*)(Ag1 + ko);
            pb0 = *(const uint4*)(Bg0 + ko);
            pb1 = *(const uint4*)(Bg1 + ko);
        }
        #pragma unroll
        for (int kk = 0; kk < 32; kk += 16) {
            unsigned aF[4][4], bF[4][2];
            #pragma unroll
            for (int im = 0; im < 4; im++) {
                unsigned addr = smem_u32(&As[buf][wm0 + im * 16 + rA][kk + cA]);
                ldsm_x4(aF[im][0], aF[im][1], aF[im][2], aF[im][3], addr);
            }
            #pragma unroll
            for (int in2 = 0; in2 < 2; in2++) {
                unsigned addr = smem_u32(&Bs[buf][wn0 + in2 * 16 + rB][kk + cB]);
                ldsm_x4(bF[in2 * 2][0], bF[in2 * 2][1],
                        bF[in2 * 2 + 1][0], bF[in2 * 2 + 1][1], addr);
            }
            #pragma unroll
            for (int im = 0; im < 4; im++)
                #pragma unroll
                for (int in = 0; in < 4; in++)
                    mma16816(acc[im][in], aF[im], bF[in]);
        }
        if (kt + 1 < NT) {
            *(uint4*)&As[buf ^ 1][r0v][c0v] = pa0;
            *(uint4*)&As[buf ^ 1][r1v][c1v] = pa1;
            *(uint4*)&Bs[buf ^ 1][r0v][c0v] = pb0;
            *(uint4*)&Bs[buf ^ 1][r1v][c1v] = pb1;
        }
        __syncthreads();
    }

    // epilogue with column scale
    const int g  = lane >> 2;
    const int i2 = (lane & 3) * 2;
    #pragma unroll
    for (int im = 0; im < 4; im++) {
        #pragma unroll
        for (int in = 0; in < 4; in++) {
            int col = bN + wn0 + in * 8 + i2;
            float cs0 = colScale[col], cs1 = colScale[col + 1];
            int row = bM + wm0 + im * 16 + g;
            float2 v0w = make_float2(acc[im][in][0] * cs0, acc[im][in][1] * cs1);
            float2 v1w = make_float2(acc[im][in][2] * cs0, acc[im][in][3] * cs1);
            *(float2*)&C[(size_t)row * NST + col]       = v0w;
            *(float2*)&C[(size_t)(row + 8) * NST + col] = v1w;
        }
    }
}

// ---------------- top-32 screening per row (ties -> lower index) ----------------
__device__ __forceinline__ bool better(float v1, int i1, float v2, int i2) {
    return (v1 > v2) || (v1 == v2 && i1 < i2);
}

__global__ __launch_bounds__(128) void screen_kernel(const float* __restrict__ S,
                                                     int* __restrict__ cand) {
    __shared__ float sv[128 * NCAND];
    __shared__ int   si[128 * NCAND];
    int b = blockIdx.x;
    const float* row = S + (size_t)b * NST;
    float lv[NCAND]; int li[NCAND];
    #pragma unroll
    for (int k = 0; k < NCAND; k++) { lv[k] = -1e30f; li[k] = 0x7fffffff; }
    float thr = -1e30f; int thrIdx = 0x7fffffff;
    for (int j = threadIdx.x; j < NST; j += 128) {
        float v = row[j];
        if (better(v, j, thr, thrIdx)) {
            int p = NCAND - 1;
            while (p > 0 && better(v, j, lv[p - 1], li[p - 1])) {
                lv[p] = lv[p - 1]; li[p] = li[p - 1]; p--;
            }
            lv[p] = v; li[p] = j;
            thr = lv[NCAND - 1]; thrIdx = li[NCAND - 1];
        }
    }
    #pragma unroll
    for (int k = 0; k < NCAND; k++) {
        sv[threadIdx.x * NCAND + k] = lv[k];
        si[threadIdx.x * NCAND + k] = li[k];
    }
    __syncthreads();
    for (int s = 64; s > 0; s >>= 1) {
        if (threadIdx.x < s) {
            float* pa  = &sv[threadIdx.x * NCAND];
            int*   pai = &si[threadIdx.x * NCAND];
            float* pb  = &sv[(threadIdx.x + s) * NCAND];
            int*   pbi = &si[(threadIdx.x + s) * NCAND];
            float mv[NCAND]; int mi[NCAND];
            int ia = 0, ib = 0;
            #pragma unroll
            for (int k = 0; k < NCAND; k++) {
                bool takeA = (ib >= NCAND) ||
                             (ia < NCAND && better(pa[ia], pai[ia], pb[ib], pbi[ib]));
                if (takeA) { mv[k] = pa[ia]; mi[k] = pai[ia]; ia++; }
                else       { mv[k] = pb[ib]; mi[k] = pbi[ib]; ib++; }
            }
            #pragma unroll
            for (int k = 0; k < NCAND; k++) { pa[k] = mv[k]; pai[k] = mi[k]; }
        }
        __syncthreads();
    }
    if (threadIdx.x < NCAND) cand[b * NCAND + threadIdx.x] = si[threadIdx.x];
}

// ---------------- exact fp64 rescore of 32 candidates + top-8 + softmax ----------------
__global__ __launch_bounds__(1024) void rescore_kernel(
    const float* __restrict__ q, const float* __restrict__ keys,
    const int* __restrict__ cand,
    const double* __restrict__ qinvd, const double* __restrict__ kinvd,
    const double* __restrict__ wd, const double* __restrict__ Sd,
    float* __restrict__ attn, int* __restrict__ topi) {
    __shared__ double ssim[NCAND];
    __shared__ int    sidx[NCAND];
    int b = blockIdx.x;
    int wid = threadIdx.x / 32;
    int lid = threadIdx.x % 32;

    int ci = cand[b * NCAND + wid];
    const float* qrow = q + (size_t)b * HD;
    const float* krow = keys + (size_t)ci * HD;
    double acc = 0.0;
    #pragma unroll
    for (int it = 0; it < HD / 32; it++) {
        int h = it * 32 + lid;
        acc += (double)qrow[h] * (double)krow[h];
    }
    #pragma unroll
    for (int off = 16; off > 0; off >>= 1)
        acc += __shfl_down_sync(0xffffffffu, acc, off);
    if (lid == 0) {
        ssim[wid] = acc * qinvd[b] * kinvd[ci] * (wd[ci] / Sd[0]);
        sidx[wid] = ci;
    }
    __syncthreads();

    if (threadIdx.x == 0) {
        double v[NCAND]; int ix[NCAND]; bool used[NCAND];
        #pragma unroll
        for (int k = 0; k < NCAND; k++) { v[k] = ssim[k]; ix[k] = sidx[k]; used[k] = false; }
        double tv[TOPK]; int ti[TOPK];
        for (int k = 0; k < TOPK; k++) {
            int best = -1;
            for (int m = 0; m < NCAND; m++) {
                if (used[m]) continue;
                if (best < 0 || v[m] > v[best] || (v[m] == v[best] && ix[m] < ix[best]))
                    best = m;
            }
            used[best] = true;
            tv[k] = v[best]; ti[k] = ix[best];
        }
        double mx = tv[0];
        for (int k = 1; k < TOPK; k++) mx = fmax(mx, tv[k]);
        double e[TOPK], s = 0.0;
        for (int k = 0; k < TOPK; k++) { e[k] = exp(tv[k] - mx); s += e[k]; }
        double inv = 1.0 / s;
        for (int k = 0; k < TOPK; k++) {
            attn[b * TOPK + k] = (float)(e[k] * inv);
            topi[b * TOPK + k] = ti[k];
        }
    }
}

// ---------------- combine: u_b = sum_k attn * store[idx] ----------------
__global__ void combine_kernel(const float* __restrict__ attn, const int* __restrict__ topi,
                               const float* __restrict__ store, float* __restrict__ u) {
    int b = blockIdx.x;
    float a[TOPK]; const float* rows[TOPK];
    #pragma unroll
    for (int k = 0; k < TOPK; k++) {
        a[k] = attn[b * TOPK + k];
        rows[k] = store + (size_t)topi[b * TOPK + k] * HD;
    }
    for (int h = threadIdx.x; h < HD; h += 128) {
        float acc = 0.0f;
        #pragma unroll
        for (int k = 0; k < TOPK; k++) acc += a[k] * rows[k][h];
        u[(size_t)b * HD + h] = acc;
    }
}

// ---------------- host launcher ----------------
extern "C" void kernel_launch(void* const* d_in, const int* in_sizes, int n_in,
                              void* d_out, int out_size) {
    const float* query      = (const float*)d_in[0];
    const float* store      = (const float*)d_in[1];
    const float* importance = (const float*)d_in[2];
    const float* timestamps = (const float*)d_in[3];
    const float* Wk         = (const float*)d_in[4];
    const float* Wv         = (const float*)d_in[5];
    const float* Wo         = (const float*)d_in[6];
    float* out = (float*)d_out;

    float *WkT, *WvT, *WoT, *keys, *scores, *qk, *qinvf, *cf, *attn, *u, *t;
    __nv_bfloat16 *storebf, *qkbf;
    double *qinvd, *wd, *kinvd, *partiald, *Sd;
    int *cand, *topi;
    cudaGetSymbolAddress((void**)&WkT,     g_WkT);
    cudaGetSymbolAddress((void**)&WvT,     g_WvT);
    cudaGetSymbolAddress((void**)&WoT,     g_WoT);
    cudaGetSymbolAddress((void**)&keys,    g_keys);
    cudaGetSymbolAddress((void**)&scores,  g_scores);
    cudaGetSymbolAddress((void**)&storebf, g_storebf);
    cudaGetSymbolAddress((void**)&qkbf,    g_qkbf);
    cudaGetSymbolAddress((void**)&qk,      g_qk);
    cudaGetSymbolAddress((void**)&qinvf,   g_qinvf);
    cudaGetSymbolAddress((void**)&qinvd,   g_qinvd);
    cudaGetSymbolAddress((void**)&wd,      g_wd);
    cudaGetSymbolAddress((void**)&kinvd,   g_kinvd);
    cudaGetSymbolAddress((void**)&cf,      g_cf);
    cudaGetSymbolAddress((void**)&partiald,g_partiald);
    cudaGetSymbolAddress((void**)&Sd,      g_Sd);
    cudaGetSymbolAddress((void**)&cand,    g_cand);
    cudaGetSymbolAddress((void**)&attn,    g_attn);
    cudaGetSymbolAddress((void**)&topi,    g_topi);
    cudaGetSymbolAddress((void**)&u,       g_u);
    cudaGetSymbolAddress((void**)&t,       g_t);

    dim3 tb(32, 8);
    transpose_kernel<<<dim3(HD / 32, HD / 32), tb>>>(Wk, WkT, HD, HD);
    transpose_kernel<<<dim3(HD / 32, HD / 32), tb>>>(Wv, WvT, HD, HD);
    transpose_kernel<<<dim3(HD / 32, HD / 32), tb>>>(Wo, WoT, HD, HD);

    // store -> bf16 for tensor-core screening
    {
        size_t n4 = ((size_t)NST * HD) / 4;
        tobf16_kernel<<<(unsigned)((n4 + 255) / 256), 256>>>(store, storebf, n4);
    }

    weight_partial_kernel<<<256, 256>>>(importance, timestamps, wd, partiald);
    weight_sum_kernel<<<1, 256>>>(partiald, Sd);
    qinv_kernel<<<BQ, 128>>>(query, qinvf, qinvd);

    // keys = store @ Wk^T   [65536 x 1024]  (fp32 precision required for rescore)
    sgemm_kernel<<<dim3(HD / 128, NST / 128), 256>>>(store, WkT, keys, NST, HD, HD, nullptr, nullptr);
    cscale_kernel<<<NST, 128>>>(keys, wd, Sd, kinvd, cf);

    // qk = (query / ||q||) @ Wk   [2048 x 1024]
    sgemm_kernel<<<dim3(HD / 128, BQ / 128), 256>>>(query, Wk, qk, BQ, HD, HD, qinvf, nullptr);
    {
        size_t n4 = ((size_t)BQ * HD) / 4;
        tobf16_kernel<<<(unsigned)((n4 + 255) / 256), 256>>>(qk, qkbf, n4);
    }

    // screening scores = qk_bf @ store_bf^T, column-scaled   [2048 x 65536]
    scores_bf16_kernel<<<dim3(NST / 128, BQ / 128), 256>>>(qkbf, storebf, cf, scores);

    screen_kernel<<<BQ, 128>>>(scores, cand);
    rescore_kernel<<<BQ, 1024>>>(query, keys, cand, qinvd, kinvd, wd, Sd, attn, topi);
    combine_kernel<<<BQ, 128>>>(attn, topi, store, u);

    // t = u @ Wv^T ; out = t @ Wo^T
    sgemm_kernel<<<dim3(HD / 128, BQ / 128), 256>>>(u, WvT, t, BQ, HD, HD, nullptr, nullptr);
    sgemm_kernel<<<dim3(HD / 128, BQ / 128), 256>>>(t, WoT, out, BQ, HD, HD, nullptr, nullptr);
}

// round 5
// speedup vs baseline: 1.0044x; 1.0044x over previous
#include <cuda_runtime.h>
#include <cuda_bf16.h>
#include <math.h>

#define BQ   2048
#define NST  65536
#define HD   1024
#define TOPK 8
#define NCAND 32

// ---------------- scratch (static device globals; no runtime allocation) ----------------
__device__ float          g_WkT[HD * HD];
__device__ float          g_WvT[HD * HD];
__device__ float          g_WoT[HD * HD];
__device__ float          g_keys[(size_t)NST * HD];          // 256 MB
__device__ float          g_scores[(size_t)BQ * NST];        // 512 MB (unscaled dots)
__device__ __nv_bfloat16  g_storebf[(size_t)NST * HD];       // 128 MB
__device__ __nv_bfloat16  g_qkbf[BQ * HD];
__device__ float          g_qk[BQ * HD];
__device__ float          g_qinvf[BQ];
__device__ double         g_qinvd[BQ];
__device__ double         g_wd[NST];
__device__ double         g_kinvd[NST];
__device__ float          g_cf[NST];
__device__ double         g_partiald[256];
__device__ double         g_Sd[1];
__device__ int            g_cand[BQ * NCAND];
__device__ float          g_attn[BQ * TOPK];
__device__ int            g_topi[BQ * TOPK];
__device__ float          g_u[BQ * HD];
__device__ float          g_t[BQ * HD];

// ---------------- small helpers ----------------
__device__ __forceinline__ unsigned smem_u32(const void* p) {
    return (unsigned)__cvta_generic_to_shared(p);
}

__device__ __forceinline__ void cp_async16(unsigned dst, const void* src) {
    asm volatile("cp.async.cg.shared.global [%0], [%1], 16;\n" :: "r"(dst), "l"(src));
}
__device__ __forceinline__ void cp_commit() {
    asm volatile("cp.async.commit_group;\n" ::: "memory");
}
template <int N>
__device__ __forceinline__ void cp_wait() {
    asm volatile("cp.async.wait_group %0;\n" :: "n"(N) : "memory");
}

__device__ __forceinline__ void ldsm_x4(unsigned& r0, unsigned& r1, unsigned& r2, unsigned& r3,
                                        unsigned addr) {
    asm volatile("ldmatrix.sync.aligned.m8n8.x4.shared.b16 {%0,%1,%2,%3}, [%4];"
                 : "=r"(r0), "=r"(r1), "=r"(r2), "=r"(r3) : "r"(addr));
}

__device__ __forceinline__ void mma16816(float* d, const unsigned* a, const unsigned* b) {
    asm volatile(
        "mma.sync.aligned.m16n8k16.row.col.f32.bf16.bf16.f32 "
        "{%0,%1,%2,%3}, {%4,%5,%6,%7}, {%8,%9}, {%0,%1,%2,%3};"
        : "+f"(d[0]), "+f"(d[1]), "+f"(d[2]), "+f"(d[3])
        : "r"(a[0]), "r"(a[1]), "r"(a[2]), "r"(a[3]), "r"(b[0]), "r"(b[1]));
}

// ---------------- fp32 -> bf16 conversion ----------------
__global__ void tobf16_kernel(const float* __restrict__ in, __nv_bfloat16* __restrict__ out,
                              size_t n4) {
    size_t i = (size_t)blockIdx.x * blockDim.x + threadIdx.x;
    if (i >= n4) return;
    float4 v = ((const float4*)in)[i];
    __nv_bfloat162* o2 = (__nv_bfloat162*)out;
    o2[i * 2 + 0] = __floats2bfloat162_rn(v.x, v.y);
    o2[i * 2 + 1] = __floats2bfloat162_rn(v.z, v.w);
}

// ---------------- transpose (dims multiples of 32) ----------------
__global__ void transpose_kernel(const float* __restrict__ in, float* __restrict__ out,
                                 int rows, int cols) {
    __shared__ float tile[32][33];
    int x0 = blockIdx.x * 32;
    int y0 = blockIdx.y * 32;
    int tx = threadIdx.x, ty = threadIdx.y;
    #pragma unroll
    for (int r = ty; r < 32; r += 8)
        tile[r][tx] = in[(size_t)(y0 + r) * cols + (x0 + tx)];
    __syncthreads();
    #pragma unroll
    for (int r = ty; r < 32; r += 8)
        out[(size_t)(x0 + r) * rows + (y0 + tx)] = tile[tx][r];
}

// ---------------- weights in fp64 + partial sums ----------------
__global__ void weight_partial_kernel(const float* __restrict__ imp,
                                      const float* __restrict__ ts,
                                      double* __restrict__ wd,
                                      double* __restrict__ partial) {
    __shared__ double sm[256];
    int j = blockIdx.x * 256 + threadIdx.x;
    double age = 1.0 - (double)ts[j];
    double r = exp(-fabs(age) * 0.01);
    double wv = r * ((double)imp[j] + 1.0);
    wd[j] = wv;
    sm[threadIdx.x] = wv;
    __syncthreads();
    for (int s = 128; s > 0; s >>= 1) {
        if (threadIdx.x < s) sm[threadIdx.x] += sm[threadIdx.x + s];
        __syncthreads();
    }
    if (threadIdx.x == 0) partial[blockIdx.x] = sm[0];
}

__global__ void weight_sum_kernel(const double* __restrict__ partial, double* __restrict__ S) {
    __shared__ double sm[256];
    sm[threadIdx.x] = partial[threadIdx.x];
    __syncthreads();
    for (int s = 128; s > 0; s >>= 1) {
        if (threadIdx.x < s) sm[threadIdx.x] += sm[threadIdx.x + s];
        __syncthreads();
    }
    if (threadIdx.x == 0) S[0] = sm[0] + 1e-8;
}

// ---------------- per-row 1/max(||q||, eps) in fp64 ----------------
__global__ void qinv_kernel(const float* __restrict__ q,
                            float* __restrict__ qinvf, double* __restrict__ qinvd) {
    __shared__ double sm[128];
    int b = blockIdx.x;
    const float* row = q + (size_t)b * HD;
    double acc = 0.0;
    for (int h = threadIdx.x; h < HD; h += 128) { double v = row[h]; acc += v * v; }
    sm[threadIdx.x] = acc;
    __syncthreads();
    for (int s = 64; s > 0; s >>= 1) {
        if (threadIdx.x < s) sm[threadIdx.x] += sm[threadIdx.x + s];
        __syncthreads();
    }
    if (threadIdx.x == 0) {
        double n = sqrt(sm[0]);
        double inv = 1.0 / fmax(n, 1e-12);
        qinvd[b] = inv;
        qinvf[b] = (float)inv;
    }
}

// ---------------- key norms (fp64) + screening column scale ----------------
__global__ void cscale_kernel(const float* __restrict__ keys, const double* __restrict__ wd,
                              const double* __restrict__ S,
                              double* __restrict__ kinvd, float* __restrict__ cf) {
    __shared__ double sm[128];
    int j = blockIdx.x;
    const float* row = keys + (size_t)j * HD;
    double acc = 0.0;
    for (int h = threadIdx.x; h < HD; h += 128) { double v = row[h]; acc += v * v; }
    sm[threadIdx.x] = acc;
    __syncthreads();
    for (int s = 64; s > 0; s >>= 1) {
        if (threadIdx.x < s) sm[threadIdx.x] += sm[threadIdx.x + s];
        __syncthreads();
    }
    if (threadIdx.x == 0) {
        double n = sqrt(sm[0]);
        double inv = 1.0 / fmax(n, 1e-12);
        kinvd[j] = inv;
        cf[j] = (float)(wd[j] / S[0] * inv);
    }
}

// ---------------- generic fp32 SGEMM: C[M,Nn] = A[M,Kk] @ B[Kk,Nn] ----------------
__global__ __launch_bounds__(256) void sgemm_kernel(
    const float* __restrict__ A, const float* __restrict__ Bm, float* __restrict__ C,
    int M, int Nn, int Kk,
    const float* __restrict__ rowScale, const float* __restrict__ colScale) {
    __shared__ float As[8][128];
    __shared__ float Bs[8][128];
    const int tid  = threadIdx.x;
    const int crow = blockIdx.y * 128;
    const int ccol = blockIdx.x * 128;
    const int tr = (tid / 16) * 8;
    const int tc = (tid % 16) * 8;
    const int aRow = tid >> 1, aCol = (tid & 1) * 4;
    const int bRow = tid >> 5, bCol = (tid & 31) * 4;
    const float* Ag = A + (size_t)(crow + aRow) * Kk + aCol;
    const float* Bg = Bm + (size_t)bRow * Nn + ccol + bCol;

    float acc[8][8];
    #pragma unroll
    for (int i = 0; i < 8; i++)
        #pragma unroll
        for (int j = 0; j < 8; j++) acc[i][j] = 0.0f;

    for (int k0 = 0; k0 < Kk; k0 += 8) {
        float4 av = *(const float4*)(Ag + k0);
        As[aCol + 0][aRow] = av.x;
        As[aCol + 1][aRow] = av.y;
        As[aCol + 2][aRow] = av.z;
        As[aCol + 3][aRow] = av.w;
        float4 bv = *(const float4*)(Bg + (size_t)k0 * Nn);
        *(float4*)(&Bs[bRow][bCol]) = bv;
        __syncthreads();
        #pragma unroll
        for (int k = 0; k < 8; k++) {
            float ar[8], br[8];
            *(float4*)(ar)     = *(const float4*)(&As[k][tr]);
            *(float4*)(ar + 4) = *(const float4*)(&As[k][tr + 4]);
            *(float4*)(br)     = *(const float4*)(&Bs[k][tc]);
            *(float4*)(br + 4) = *(const float4*)(&Bs[k][tc + 4]);
            #pragma unroll
            for (int i = 0; i < 8; i++)
                #pragma unroll
                for (int j = 0; j < 8; j++)
                    acc[i][j] += ar[i] * br[j];
        }
        __syncthreads();
    }

    #pragma unroll
    for (int i = 0; i < 8; i++) {
        float rs = rowScale ? rowScale[crow + tr + i] : 1.0f;
        float v[8];
        #pragma unroll
        for (int j = 0; j < 8; j++) {
            v[j] = acc[i][j] * rs;
            if (colScale) v[j] *= colScale[ccol + tc + j];
        }
        float* Crow = C + (size_t)(crow + tr + i) * Nn + ccol + tc;
        *(float4*)(Crow)     = *(float4*)(v);
        *(float4*)(Crow + 4) = *(float4*)(v + 4);
    }
}

// ---------------- bf16 tensor-core screening GEMM (cp.async, no colScale) ----------------
// C[M,N] = A[M,K] @ B[N,K]^T.  M=BQ, N=NST, K=HD.
// Tiles: 128x128x32, 8 warps of 64x32, m16n8k16 HMMA, 2-stage cp.async pipeline.
__global__ __launch_bounds__(256, 2) void scores_bf16_kernel(
    const __nv_bfloat16* __restrict__ A,   // [BQ][HD]
    const __nv_bfloat16* __restrict__ B,   // [NST][HD]
    float* __restrict__ C)                 // [BQ][NST]
{
    __shared__ __align__(16) __nv_bfloat16 As[2][128][40];  // 80B pitch: ldmatrix conflict-free
    __shared__ __align__(16) __nv_bfloat16 Bs[2][128][40];

    const int tid  = threadIdx.x;
    const int lane = tid & 31;
    const int wid  = tid >> 5;
    const int wm0  = (wid >> 2) * 64;
    const int wn0  = (wid & 3) * 32;
    const int bM   = blockIdx.y * 128;
    const int bN   = blockIdx.x * 128;

    // each thread copies two 16B chunks per tile (256 threads cover 128x32 bf16)
    const int r0v = tid >> 2,           c0v = (tid & 3) * 8;
    const int r1v = (tid + 256) >> 2,   c1v = (tid & 3) * 8;
    const __nv_bfloat16* Ag0 = A + (size_t)(bM + r0v) * HD + c0v;
    const __nv_bfloat16* Ag1 = A + (size_t)(bM + r1v) * HD + c1v;
    const __nv_bfloat16* Bg0 = B + (size_t)(bN + r0v) * HD + c0v;
    const __nv_bfloat16* Bg1 = B + (size_t)(bN + r1v) * HD + c1v;

    // ldmatrix source coordinates
    const int rA = (lane & 7) + ((lane >> 3) & 1) * 8;
    const int cA = (lane >> 4) * 8;
    const int rB = (lane & 7) + (lane >> 4) * 8;
    const int cB = ((lane >> 3) & 1) * 8;

    float acc[4][4][4];
    #pragma unroll
    for (int im = 0; im < 4; im++)
        #pragma unroll
        for (int in = 0; in < 4; in++)
            #pragma unroll
            for (int e = 0; e < 4; e++) acc[im][in][e] = 0.0f;

    // prologue: stage 0
    cp_async16(smem_u32(&As[0][r0v][c0v]), Ag0);
    cp_async16(smem_u32(&As[0][r1v][c1v]), Ag1);
    cp_async16(smem_u32(&Bs[0][r0v][c0v]), Bg0);
    cp_async16(smem_u32(&Bs[0][r1v][c1v]), Bg1);
    cp_commit();

    const int NT = HD / 32;
    for (int kt = 0; kt < NT; kt++) {
        const int buf = kt & 1;
        if (kt + 1 < NT) {
            const int ko = (kt + 1) * 32;
            cp_async16(smem_u32(&As[buf ^ 1][r0v][c0v]), Ag0 + ko);
            cp_async16(smem_u32(&As[buf ^ 1][r1v][c1v]), Ag1 + ko);
            cp_async16(smem_u32(&Bs[buf ^ 1][r0v][c0v]), Bg0 + ko);
            cp_async16(smem_u32(&Bs[buf ^ 1][r1v][c1v]), Bg1 + ko);
            cp_commit();
            cp_wait<1>();   // stage kt complete; stage kt+1 may be in flight
        } else {
            cp_wait<0>();
        }
        __syncthreads();

        #pragma unroll
        for (int kk = 0; kk < 32; kk += 16) {
            unsigned aF[4][4], bF[4][2];
            #pragma unroll
            for (int im = 0; im < 4; im++) {
                unsigned addr = smem_u32(&As[buf][wm0 + im * 16 + rA][kk + cA]);
                ldsm_x4(aF[im][0], aF[im][1], aF[im][2], aF[im][3], addr);
            }
            #pragma unroll
            for (int in2 = 0; in2 < 2; in2++) {
                unsigned addr = smem_u32(&Bs[buf][wn0 + in2 * 16 + rB][kk + cB]);
                ldsm_x4(bF[in2 * 2][0], bF[in2 * 2][1],
                        bF[in2 * 2 + 1][0], bF[in2 * 2 + 1][1], addr);
            }
            #pragma unroll
            for (int im = 0; im < 4; im++)
                #pragma unroll
                for (int in = 0; in < 4; in++)
                    mma16816(acc[im][in], aF[im], bF[in]);
        }
        __syncthreads();   // all reads of buf done before next iter overwrites it
    }

    // epilogue (raw dots; cf applied in screen_kernel)
    const int g  = lane >> 2;
    const int i2 = (lane & 3) * 2;
    #pragma unroll
    for (int im = 0; im < 4; im++) {
        #pragma unroll
        for (int in = 0; in < 4; in++) {
            int col = bN + wn0 + in * 8 + i2;
            int row = bM + wm0 + im * 16 + g;
            *(float2*)&C[(size_t)row * NST + col]       = make_float2(acc[im][in][0], acc[im][in][1]);
            *(float2*)&C[(size_t)(row + 8) * NST + col] = make_float2(acc[im][in][2], acc[im][in][3]);
        }
    }
}

// ---------------- top-32 screening per row (cf applied here; ties -> lower index) ----------------
__device__ __forceinline__ bool better(float v1, int i1, float v2, int i2) {
    return (v1 > v2) || (v1 == v2 && i1 < i2);
}

__global__ __launch_bounds__(128) void screen_kernel(const float* __restrict__ S,
                                                     const float* __restrict__ cf,
                                                     int* __restrict__ cand) {
    __shared__ float sv[128 * NCAND];
    __shared__ int   si[128 * NCAND];
    int b = blockIdx.x;
    const float* row = S + (size_t)b * NST;
    float lv[NCAND]; int li[NCAND];
    #pragma unroll
    for (int k = 0; k < NCAND; k++) { lv[k] = -1e30f; li[k] = 0x7fffffff; }
    float thr = -1e30f; int thrIdx = 0x7fffffff;
    for (int j = threadIdx.x; j < NST; j += 128) {
        float v = row[j] * cf[j];
        if (better(v, j, thr, thrIdx)) {
            int p = NCAND - 1;
            while (p > 0 && better(v, j, lv[p - 1], li[p - 1])) {
                lv[p] = lv[p - 1]; li[p] = li[p - 1]; p--;
            }
            lv[p] = v; li[p] = j;
            thr = lv[NCAND - 1]; thrIdx = li[NCAND - 1];
        }
    }
    #pragma unroll
    for (int k = 0; k < NCAND; k++) {
        sv[threadIdx.x * NCAND + k] = lv[k];
        si[threadIdx.x * NCAND + k] = li[k];
    }
    __syncthreads();
    for (int s = 64; s > 0; s >>= 1) {
        if (threadIdx.x < s) {
            float* pa  = &sv[threadIdx.x * NCAND];
            int*   pai = &si[threadIdx.x * NCAND];
            float* pb  = &sv[(threadIdx.x + s) * NCAND];
            int*   pbi = &si[(threadIdx.x + s) * NCAND];
            float mv[NCAND]; int mi[NCAND];
            int ia = 0, ib = 0;
            #pragma unroll
            for (int k = 0; k < NCAND; k++) {
                bool takeA = (ib >= NCAND) ||
                             (ia < NCAND && better(pa[ia], pai[ia], pb[ib], pbi[ib]));
                if (takeA) { mv[k] = pa[ia]; mi[k] = pai[ia]; ia++; }
                else       { mv[k] = pb[ib]; mi[k] = pbi[ib]; ib++; }
            }
            #pragma unroll
            for (int k = 0; k < NCAND; k++) { pa[k] = mv[k]; pai[k] = mi[k]; }
        }
        __syncthreads();
    }
    if (threadIdx.x < NCAND) cand[b * NCAND + threadIdx.x] = si[threadIdx.x];
}

// ---------------- exact fp64 rescore of 32 candidates + top-8 + softmax ----------------
__global__ __launch_bounds__(1024) void rescore_kernel(
    const float* __restrict__ q, const float* __restrict__ keys,
    const int* __restrict__ cand,
    const double* __restrict__ qinvd, const double* __restrict__ kinvd,
    const double* __restrict__ wd, const double* __restrict__ Sd,
    float* __restrict__ attn, int* __restrict__ topi) {
    __shared__ double ssim[NCAND];
    __shared__ int    sidx[NCAND];
    int b = blockIdx.x;
    int wid = threadIdx.x / 32;
    int lid = threadIdx.x % 32;

    int ci = cand[b * NCAND + wid];
    const float* qrow = q + (size_t)b * HD;
    const float* krow = keys + (size_t)ci * HD;
    double acc = 0.0;
    #pragma unroll
    for (int it = 0; it < HD / 32; it++) {
        int h = it * 32 + lid;
        acc += (double)qrow[h] * (double)krow[h];
    }
    #pragma unroll
    for (int off = 16; off > 0; off >>= 1)
        acc += __shfl_down_sync(0xffffffffu, acc, off);
    if (lid == 0) {
        ssim[wid] = acc * qinvd[b] * kinvd[ci] * (wd[ci] / Sd[0]);
        sidx[wid] = ci;
    }
    __syncthreads();

    if (threadIdx.x == 0) {
        double v[NCAND]; int ix[NCAND]; bool used[NCAND];
        #pragma unroll
        for (int k = 0; k < NCAND; k++) { v[k] = ssim[k]; ix[k] = sidx[k]; used[k] = false; }
        double tv[TOPK]; int ti[TOPK];
        for (int k = 0; k < TOPK; k++) {
            int best = -1;
            for (int m = 0; m < NCAND; m++) {
                if (used[m]) continue;
                if (best < 0 || v[m] > v[best] || (v[m] == v[best] && ix[m] < ix[best]))
                    best = m;
            }
            used[best] = true;
            tv[k] = v[best]; ti[k] = ix[best];
        }
        double mx = tv[0];
        for (int k = 1; k < TOPK; k++) mx = fmax(mx, tv[k]);
        double e[TOPK], s = 0.0;
        for (int k = 0; k < TOPK; k++) { e[k] = exp(tv[k] - mx); s += e[k]; }
        double inv = 1.0 / s;
        for (int k = 0; k < TOPK; k++) {
            attn[b * TOPK + k] = (float)(e[k] * inv);
            topi[b * TOPK + k] = ti[k];
        }
    }
}

// ---------------- combine: u_b = sum_k attn * store[idx] ----------------
__global__ void combine_kernel(const float* __restrict__ attn, const int* __restrict__ topi,
                               const float* __restrict__ store, float* __restrict__ u) {
    int b = blockIdx.x;
    float a[TOPK]; const float* rows[TOPK];
    #pragma unroll
    for (int k = 0; k < TOPK; k++) {
        a[k] = attn[b * TOPK + k];
        rows[k] = store + (size_t)topi[b * TOPK + k] * HD;
    }
    for (int h = threadIdx.x; h < HD; h += 128) {
        float acc = 0.0f;
        #pragma unroll
        for (int k = 0; k < TOPK; k++) acc += a[k] * rows[k][h];
        u[(size_t)b * HD + h] = acc;
    }
}

// ---------------- host launcher ----------------
extern "C" void kernel_launch(void* const* d_in, const int* in_sizes, int n_in,
                              void* d_out, int out_size) {
    const float* query      = (const float*)d_in[0];
    const float* store      = (const float*)d_in[1];
    const float* importance = (const float*)d_in[2];
    const float* timestamps = (const float*)d_in[3];
    const float* Wk         = (const float*)d_in[4];
    const float* Wv         = (const float*)d_in[5];
    const float* Wo         = (const float*)d_in[6];
    float* out = (float*)d_out;

    float *WkT, *WvT, *WoT, *keys, *scores, *qk, *qinvf, *cf, *attn, *u, *t;
    __nv_bfloat16 *storebf, *qkbf;
    double *qinvd, *wd, *kinvd, *partiald, *Sd;
    int *cand, *topi;
    cudaGetSymbolAddress((void**)&WkT,     g_WkT);
    cudaGetSymbolAddress((void**)&WvT,     g_WvT);
    cudaGetSymbolAddress((void**)&WoT,     g_WoT);
    cudaGetSymbolAddress((void**)&keys,    g_keys);
    cudaGetSymbolAddress((void**)&scores,  g_scores);
    cudaGetSymbolAddress((void**)&storebf, g_storebf);
    cudaGetSymbolAddress((void**)&qkbf,    g_qkbf);
    cudaGetSymbolAddress((void**)&qk,      g_qk);
    cudaGetSymbolAddress((void**)&qinvf,   g_qinvf);
    cudaGetSymbolAddress((void**)&qinvd,   g_qinvd);
    cudaGetSymbolAddress((void**)&wd,      g_wd);
    cudaGetSymbolAddress((void**)&kinvd,   g_kinvd);
    cudaGetSymbolAddress((void**)&cf,      g_cf);
    cudaGetSymbolAddress((void**)&partiald,g_partiald);
    cudaGetSymbolAddress((void**)&Sd,      g_Sd);
    cudaGetSymbolAddress((void**)&cand,    g_cand);
    cudaGetSymbolAddress((void**)&attn,    g_attn);
    cudaGetSymbolAddress((void**)&topi,    g_topi);
    cudaGetSymbolAddress((void**)&u,       g_u);
    cudaGetSymbolAddress((void**)&t,       g_t);

    dim3 tb(32, 8);
    transpose_kernel<<<dim3(HD / 32, HD / 32), tb>>>(Wk, WkT, HD, HD);
    transpose_kernel<<<dim3(HD / 32, HD / 32), tb>>>(Wv, WvT, HD, HD);
    transpose_kernel<<<dim3(HD / 32, HD / 32), tb>>>(Wo, WoT, HD, HD);

    // store -> bf16 for tensor-core screening
    {
        size_t n4 = ((size_t)NST * HD) / 4;
        tobf16_kernel<<<(unsigned)((n4 + 255) / 256), 256>>>(store, storebf, n4);
    }

    weight_partial_kernel<<<256, 256>>>(importance, timestamps, wd, partiald);
    weight_sum_kernel<<<1, 256>>>(partiald, Sd);
    qinv_kernel<<<BQ, 128>>>(query, qinvf, qinvd);

    // qk = (query / ||q||) @ Wk   [2048 x 1024]
    sgemm_kernel<<<dim3(HD / 128, BQ / 128), 256>>>(query, Wk, qk, BQ, HD, HD, qinvf, nullptr);
    {
        size_t n4 = ((size_t)BQ * HD) / 4;
        tobf16_kernel<<<(unsigned)((n4 + 255) / 256), 256>>>(qk, qkbf, n4);
    }

    // screening dots = qk_bf @ store_bf^T   [2048 x 65536]  (unscaled)
    scores_bf16_kernel<<<dim3(NST / 128, BQ / 128), 256>>>(qkbf, storebf, scores);

    // keys = store @ Wk^T   [65536 x 1024]  (fp32 precision required for rescore)
    sgemm_kernel<<<dim3(HD / 128, NST / 128), 256>>>(store, WkT, keys, NST, HD, HD, nullptr, nullptr);
    cscale_kernel<<<NST, 128>>>(keys, wd, Sd, kinvd, cf);

    screen_kernel<<<BQ, 128>>>(scores, cf, cand);
    rescore_kernel<<<BQ, 1024>>>(query, keys, cand, qinvd, kinvd, wd, Sd, attn, topi);
    combine_kernel<<<BQ, 128>>>(attn, topi, store, u);

    // t = u @ Wv^T ; out = t @ Wo^T
    sgemm_kernel<<<dim3(HD / 128, BQ / 128), 256>>>(u, WvT, t, BQ, HD, HD, nullptr, nullptr);
    sgemm_kernel<<<dim3(HD / 128, BQ / 128), 256>>>(t, WoT, out, BQ, HD, HD, nullptr, nullptr);
}